// round 11
// baseline (speedup 1.0000x reference)
#include <cuda_runtime.h>

// StatelessConvLIF: fused 3x3 SAME conv (fp32) + LIF scan over T=8.
// x: [8,16,64,64,64] fp32, W: [128,64,3,3] fp32, out spikes: [8,16,128,64,64] fp32.
//
// R11: = R10 + weight LDS vectorization. The {w,w} pair row (80B, 16B-aligned)
// is read as 4x LDS.128 + 1x LDS.64 instead of 9x LDS.64, halving L1 wavefront
// pressure from the weight stream (R10 ncu: L1=66.3% was the top pipe).
// FFMA2 operand values/order are bit-identical to R8/R10 (same rel_err).

#define THREADS 256
#define CHUNK   4
#define XSTRIDE 36          // 34 cols padded to 36
#define XBUF    (CHUNK * 34 * XSTRIDE)   // floats per buffer = 4896
#define NCO     8
#define T_STEPS 8
#define BATCH   16
#define CIN     64
#define COUT    128
#define HW      64

typedef unsigned long long ull;

__device__ __forceinline__ ull pk2(float lo, float hi) {
    ull r; asm("mov.b64 %0, {%1, %2};" : "=l"(r) : "f"(lo), "f"(hi)); return r;
}
__device__ __forceinline__ void upk2(ull a, float& lo, float& hi) {
    asm("mov.b64 {%0, %1}, %2;" : "=f"(lo), "=f"(hi) : "l"(a));
}
__device__ __forceinline__ void ffma2(ull& d, ull a, ull b) {
    asm("fma.rn.f32x2 %0, %1, %2, %0;" : "+l"(d) : "l"(a), "l"(b));
}
__device__ __forceinline__ void cp4(unsigned dst, const float* src, unsigned sz) {
    asm volatile("cp.async.ca.shared.global [%0], [%1], 4, %2;"
                 :: "r"(dst), "l"(src), "r"(sz));
}
__device__ __forceinline__ void cp_commit() {
    asm volatile("cp.async.commit_group;");
}
__device__ __forceinline__ void cp_wait0() {
    asm volatile("cp.async.wait_group 0;");
}

__global__ __launch_bounds__(THREADS, 2)
void convlif_kernel(const float* __restrict__ x,
                    const float* __restrict__ w,
                    float* __restrict__ out)
{
    extern __shared__ float smem[];
    float* xs0 = smem;                    // buffer 0: [CHUNK][34][XSTRIDE]
    float* xs1 = smem + XBUF;             // buffer 1
    ull*   ws  = (ull*)(smem + 2 * XBUF); // [NCO][CIN][10] {w,w} pairs (80B rows, 16B aligned)

    const int tid  = threadIdx.x;
    const int lane = tid & 31;
    const int warp = tid >> 5;
    const int tx   = tid & 7;
    const int ty   = tid >> 3;
    const int h0   = (blockIdx.x >> 1) * 32;
    const int w0   = (blockIdx.x & 1) * 32;
    const int b    = blockIdx.y;
    const int cg   = blockIdx.z;

    // Weights -> smem as {w,w} pairs (visible after first loop barrier).
    {
        const float* wg = w + (size_t)cg * NCO * CIN * 9;
        for (int i = tid; i < NCO * CIN * 9; i += THREADS) {
            int cocin = i / 9, k = i - cocin * 9;
            float wv = wg[i];
            ws[cocin * 10 + k] = pk2(wv, wv);
        }
    }

    // Loader geometry (division-free): warp covers (c = warp>>1), 17 rows
    // starting at (warp&1)*17; lane covers col = lane, lanes 0/1 also 32/33.
    const int lc    = warp >> 1;               // chunk-local channel 0..3
    const int lrow0 = (warp & 1) * 17;         // 0 or 17
    const int gw_m  = w0 + lane - 1;           // main col, global
    const unsigned okw_m = ((unsigned)gw_m < HW) ? 4u : 0u;
    const int gwc_m = (gw_m < 0) ? 0 : (gw_m >= HW ? HW - 1 : gw_m);
    const int gw_t  = w0 + 32 + lane - 1;      // tail col (lanes 0,1)
    const unsigned okw_t = ((unsigned)gw_t < HW) ? 4u : 0u;
    const int gwc_t = (gw_t >= HW) ? HW - 1 : gw_t;

    unsigned smem_u32;
    {
        void* p = smem;
        asm("{ .reg .u64 t; cvta.to.shared.u64 t, %1; cvt.u32.u64 %0, t; }"
            : "=r"(smem_u32) : "l"(p));
    }

    // Prefetch one chunk: global index g in [0,128) = t*16 + ch (4 cins each).
    auto prefetch = [&](int g, int buf) {
        if (g < T_STEPS * 16) {
            const int t  = g >> 4;
            const int ch = g & 15;
            const float* xb = x + (((size_t)t * BATCH + b) * CIN + ch * CHUNK + lc) * (HW * HW);
            unsigned dst0 = smem_u32 + (unsigned)(buf * XBUF + lc * 34 * XSTRIDE) * 4u;
#pragma unroll 1
            for (int j = 0; j < 17; j++) {
                const int row = lrow0 + j;
                const int gh  = h0 + row - 1;
                const unsigned okh = ((unsigned)gh < HW) ? 4u : 0u;
                const int ghc = (gh < 0) ? 0 : (gh >= HW ? HW - 1 : gh);
                const float* srow = xb + ghc * HW;
                unsigned drow = dst0 + (unsigned)(row * XSTRIDE) * 4u;
                cp4(drow + (unsigned)lane * 4u, srow + gwc_m, okh & okw_m);
                if (lane < 2)
                    cp4(drow + (unsigned)(32 + lane) * 4u, srow + gwc_t, okh & okw_t);
            }
        }
        cp_commit();
    };

    prefetch(0, 0);

    ull v01[NCO], v23[NCO];
#pragma unroll
    for (int co = 0; co < NCO; co++) { v01[co] = 0ull; v23[co] = 0ull; }

    ull a01[NCO], a23[NCO];
#pragma unroll
    for (int co = 0; co < NCO; co++) { a01[co] = 0ull; a23[co] = 0ull; }

#pragma unroll 1
    for (int g = 0; g < T_STEPS * 16; g++) {
        cp_wait0();            // this thread's chunk-g data in smem
        __syncthreads();       // all threads' data in; prev buffer free

        prefetch(g + 1, (g + 1) & 1);

        const float* xs = (g & 1) ? xs1 : xs0;
        const int cin0 = (g & 15) * CHUNK;

#pragma unroll 1
        for (int c = 0; c < CHUNK; c++) {
            const float* xr = xs + (c * 34 + ty) * XSTRIDE + tx * 4;
            ull P[3][5];
#pragma unroll
            for (int dy = 0; dy < 3; dy++) {
                float4 a4 = *(const float4*)(xr + dy * XSTRIDE);
                float2 b2 = *(const float2*)(xr + dy * XSTRIDE + 4);
                P[dy][0] = pk2(a4.x, a4.y);
                P[dy][1] = pk2(a4.y, a4.z);
                P[dy][2] = pk2(a4.z, a4.w);
                P[dy][3] = pk2(a4.w, b2.x);
                P[dy][4] = pk2(b2.x, b2.y);
            }
            const int cin = cin0 + c;
#pragma unroll
            for (int co = 0; co < NCO; co++) {
                // Weight row: 4x LDS.128 + 1x LDS.64 (16B-aligned, stride 80B).
                const ulonglong2* wp2 = (const ulonglong2*)(ws + (co * CIN + cin) * 10);
                ulonglong2 q01 = wp2[0];
                ulonglong2 q23 = wp2[1];
                ulonglong2 q45 = wp2[2];
                ulonglong2 q67 = wp2[3];
                ull wq8 = ws[(co * CIN + cin) * 10 + 8];
                ull wq[9] = { q01.x, q01.y, q23.x, q23.y,
                              q45.x, q45.y, q67.x, q67.y, wq8 };
#pragma unroll
                for (int ky = 0; ky < 3; ky++)
#pragma unroll
                    for (int kx = 0; kx < 3; kx++) {
                        ffma2(a01[co], P[ky][kx],     wq[ky * 3 + kx]);
                        ffma2(a23[co], P[ky][kx + 2], wq[ky * 3 + kx]);
                    }
            }
        }

        if ((g & 15) == 15) {
            const int t = g >> 4;
            // LIF update + spike store (reference op order: v += (z - v)/2).
#pragma unroll
            for (int co = 0; co < NCO; co++) {
                float z0, z1, z2, z3, u0, u1, u2, u3;
                upk2(a01[co], z0, z1);
                upk2(a23[co], z2, z3);
                upk2(v01[co], u0, u1);
                upk2(v23[co], u2, u3);
                u0 += (z0 - u0) * 0.5f;
                u1 += (z1 - u1) * 0.5f;
                u2 += (z2 - u2) * 0.5f;
                u3 += (z3 - u3) * 0.5f;
                float4 s;
                s.x = (u0 >= 1.0f) ? 1.f : 0.f;  if (u0 >= 1.0f) u0 = 0.f;
                s.y = (u1 >= 1.0f) ? 1.f : 0.f;  if (u1 >= 1.0f) u1 = 0.f;
                s.z = (u2 >= 1.0f) ? 1.f : 0.f;  if (u2 >= 1.0f) u2 = 0.f;
                s.w = (u3 >= 1.0f) ? 1.f : 0.f;  if (u3 >= 1.0f) u3 = 0.f;
                v01[co] = pk2(u0, u1);
                v23[co] = pk2(u2, u3);
                a01[co] = 0ull;
                a23[co] = 0ull;
                size_t o = ((((size_t)t * BATCH + b) * COUT + cg * NCO + co) * HW + (h0 + ty)) * HW
                         + (w0 + tx * 4);
                *(float4*)(out + o) = s;
            }
        }
    }
}

extern "C" void kernel_launch(void* const* d_in, const int* in_sizes, int n_in,
                              void* d_out, int out_size)
{
    const float* x = (const float*)d_in[0];
    const float* w = (const float*)d_in[1];
    float* out     = (float*)d_out;

    const int smem_bytes = 2 * XBUF * 4        // x double buffer: 39,168 B
                         + NCO * CIN * 10 * 8; // weight pairs:     40,960 B  -> 80,128 B
    cudaFuncSetAttribute(convlif_kernel,
                         cudaFuncAttributeMaxDynamicSharedMemorySize, smem_bytes);

    dim3 grid(4 /* 2x2 spatial tiles */, BATCH, COUT / NCO);
    convlif_kernel<<<grid, THREADS, smem_bytes>>>(x, w, out);
}

// round 14
// speedup vs baseline: 1.0357x; 1.0357x over previous
#include <cuda_runtime.h>

// StatelessConvLIF: fused 3x3 SAME conv (fp32) + LIF scan over T=8.
// x: [8,16,64,64,64] fp32, W: [128,64,3,3] fp32, out spikes: [8,16,128,64,64] fp32.
//
// R14: proven R10 cp.async kernel (2481 us) + (a) 3-stage ring with
// cp.async.wait_group 1 so every prefetch gets two compute phases to land,
// (b) #pragma unroll 2 on the per-channel loop so ptxas can overlap the next
// channel's window LDS under the current FFMA2 burst. TMA path abandoned
// (two unobservable illegal-instruction rounds). Conv accumulation order is
// bit-identical to R8/R10 -> rel_err must stay 7.0777e-4.

#define THREADS 256
#define CHUNK   4
#define XSTRIDE 36                      // 34 cols padded to 36
#define XBUF    (CHUNK * 34 * XSTRIDE)  // floats per stage = 4896
#define STAGES  3
#define NCO     8
#define T_STEPS 8
#define BATCH   16
#define CIN     64
#define COUT    128
#define HW      64
#define NCHUNKS (T_STEPS * 16)          // 128

typedef unsigned long long ull;

__device__ __forceinline__ ull pk2(float lo, float hi) {
    ull r; asm("mov.b64 %0, {%1, %2};" : "=l"(r) : "f"(lo), "f"(hi)); return r;
}
__device__ __forceinline__ void upk2(ull a, float& lo, float& hi) {
    asm("mov.b64 {%0, %1}, %2;" : "=f"(lo), "=f"(hi) : "l"(a));
}
__device__ __forceinline__ void ffma2(ull& d, ull a, ull b) {
    asm("fma.rn.f32x2 %0, %1, %2, %0;" : "+l"(d) : "l"(a), "l"(b));
}
__device__ __forceinline__ void cp4(unsigned dst, const float* src, unsigned sz) {
    asm volatile("cp.async.ca.shared.global [%0], [%1], 4, %2;"
                 :: "r"(dst), "l"(src), "r"(sz));
}
__device__ __forceinline__ void cp_commit() {
    asm volatile("cp.async.commit_group;");
}
__device__ __forceinline__ void cp_wait1() {
    asm volatile("cp.async.wait_group 1;");   // allow newest group in flight
}

__global__ __launch_bounds__(THREADS, 2)
void convlif_kernel(const float* __restrict__ x,
                    const float* __restrict__ w,
                    float* __restrict__ out)
{
    extern __shared__ float smem[];
    // layout: xs[STAGES][XBUF] | ws [NCO][CIN][10] {w,w} pairs
    ull* ws = (ull*)(smem + STAGES * XBUF);

    const int tid  = threadIdx.x;
    const int lane = tid & 31;
    const int warp = tid >> 5;
    const int tx   = tid & 7;        // col-group: 4 pixels at w0 + 4*tx
    const int ty   = tid >> 3;       // row within tile: 0..31
    const int h0   = (blockIdx.x >> 1) * 32;
    const int w0   = (blockIdx.x & 1) * 32;
    const int b    = blockIdx.y;
    const int cg   = blockIdx.z;

    // Weights -> smem as {w,w} pairs (80B rows, 16B aligned). Visible to all
    // threads after the first __syncthreads inside the main loop (g=0).
    {
        const float* wg = w + (size_t)cg * NCO * CIN * 9;
        for (int i = tid; i < NCO * CIN * 9; i += THREADS) {
            int cocin = i / 9, k = i - cocin * 9;
            float wv = wg[i];
            ws[cocin * 10 + k] = pk2(wv, wv);
        }
    }

    // Loader geometry (division-free): warp covers channel c = warp>>1 and 17
    // rows starting at (warp&1)*17; lane covers col = lane (+ lanes 0/1: 32/33).
    const int lc    = warp >> 1;
    const int lrow0 = (warp & 1) * 17;
    const int gw_m  = w0 + lane - 1;
    const unsigned okw_m = ((unsigned)gw_m < HW) ? 4u : 0u;
    const int gwc_m = (gw_m < 0) ? 0 : (gw_m >= HW ? HW - 1 : gw_m);
    const int gw_t  = w0 + 32 + lane - 1;
    const unsigned okw_t = ((unsigned)gw_t < HW) ? 4u : 0u;
    const int gwc_t = (gw_t >= HW) ? HW - 1 : gw_t;

    unsigned smem_u32;
    {
        void* p = smem;
        asm("{ .reg .u64 t; cvta.to.shared.u64 t, %1; cvt.u32.u64 %0, t; }"
            : "=r"(smem_u32) : "l"(p));
    }

    // Prefetch chunk g into stage s.
    auto prefetch = [&](int g, int s) {
        if (g < NCHUNKS) {
            const int t  = g >> 4;
            const int ch = g & 15;
            const float* xb = x + (((size_t)t * BATCH + b) * CIN + ch * CHUNK + lc) * (HW * HW);
            unsigned dst0 = smem_u32 + (unsigned)(s * XBUF + lc * 34 * XSTRIDE) * 4u;
#pragma unroll 1
            for (int j = 0; j < 17; j++) {
                const int row = lrow0 + j;
                const int gh  = h0 + row - 1;
                const unsigned okh = ((unsigned)gh < HW) ? 4u : 0u;
                const int ghc = (gh < 0) ? 0 : (gh >= HW ? HW - 1 : gh);
                const float* srow = xb + ghc * HW;
                unsigned drow = dst0 + (unsigned)(row * XSTRIDE) * 4u;
                cp4(drow + (unsigned)lane * 4u, srow + gwc_m, okh & okw_m);
                if (lane < 2)
                    cp4(drow + (unsigned)(32 + lane) * 4u, srow + gwc_t, okh & okw_t);
            }
        }
        cp_commit();
    };

    // Prologue: chunks 0 and 1 into stages 0 and 1.
    prefetch(0, 0);
    prefetch(1, 1);

    ull v01[NCO], v23[NCO], a01[NCO], a23[NCO];
#pragma unroll
    for (int co = 0; co < NCO; co++) {
        v01[co] = 0ull; v23[co] = 0ull;
        a01[co] = 0ull; a23[co] = 0ull;
    }

    int buf = 0;    // consumer stage for chunk g
    int nbuf = 2;   // producer stage for chunk g+2

#pragma unroll 1
    for (int g = 0; g < NCHUNKS; g++) {
        cp_wait1();            // group g complete (g+1 may stay in flight)
        __syncthreads();       // all threads see chunk g; stage nbuf fully
                               // consumed (was chunk g-1's ... g+2's target
                               // was read during chunk g-1) -> safe to refill

        prefetch(g + 2, nbuf);
        nbuf = (nbuf == STAGES - 1) ? 0 : nbuf + 1;

        const float* xs = smem + buf * XBUF;
        const int cin0 = (g & 15) * CHUNK;

#pragma unroll 2
        for (int c = 0; c < CHUNK; c++) {
            const float* xr = xs + (c * 34 + ty) * XSTRIDE + tx * 4;
            ull P[3][5];
#pragma unroll
            for (int dy = 0; dy < 3; dy++) {
                float4 a4 = *(const float4*)(xr + dy * XSTRIDE);
                float2 b2 = *(const float2*)(xr + dy * XSTRIDE + 4);
                P[dy][0] = pk2(a4.x, a4.y);
                P[dy][1] = pk2(a4.y, a4.z);
                P[dy][2] = pk2(a4.z, a4.w);
                P[dy][3] = pk2(a4.w, b2.x);
                P[dy][4] = pk2(b2.x, b2.y);
            }
            const int cin = cin0 + c;
#pragma unroll
            for (int co = 0; co < NCO; co++) {
                const ull* wp = ws + (co * CIN + cin) * 10;
                ull wq[9];
#pragma unroll
                for (int k = 0; k < 9; k++) wq[k] = wp[k];
#pragma unroll
                for (int ky = 0; ky < 3; ky++)
#pragma unroll
                    for (int kx = 0; kx < 3; kx++) {
                        ffma2(a01[co], P[ky][kx],     wq[ky * 3 + kx]);
                        ffma2(a23[co], P[ky][kx + 2], wq[ky * 3 + kx]);
                    }
            }
        }

        if ((g & 15) == 15) {
            const int t = g >> 4;
            // LIF update + spike store (reference op order: v += (z - v)/2).
#pragma unroll
            for (int co = 0; co < NCO; co++) {
                float z0, z1, z2, z3, u0, u1, u2, u3;
                upk2(a01[co], z0, z1);
                upk2(a23[co], z2, z3);
                upk2(v01[co], u0, u1);
                upk2(v23[co], u2, u3);
                u0 += (z0 - u0) * 0.5f;
                u1 += (z1 - u1) * 0.5f;
                u2 += (z2 - u2) * 0.5f;
                u3 += (z3 - u3) * 0.5f;
                float4 s;
                s.x = (u0 >= 1.0f) ? 1.f : 0.f;  if (u0 >= 1.0f) u0 = 0.f;
                s.y = (u1 >= 1.0f) ? 1.f : 0.f;  if (u1 >= 1.0f) u1 = 0.f;
                s.z = (u2 >= 1.0f) ? 1.f : 0.f;  if (u2 >= 1.0f) u2 = 0.f;
                s.w = (u3 >= 1.0f) ? 1.f : 0.f;  if (u3 >= 1.0f) u3 = 0.f;
                v01[co] = pk2(u0, u1);
                v23[co] = pk2(u2, u3);
                a01[co] = 0ull;
                a23[co] = 0ull;
                size_t o = ((((size_t)t * BATCH + b) * COUT + cg * NCO + co) * HW + (h0 + ty)) * HW
                         + (w0 + tx * 4);
                *(float4*)(out + o) = s;
            }
        }

        buf = (buf == STAGES - 1) ? 0 : buf + 1;
    }
}

extern "C" void kernel_launch(void* const* d_in, const int* in_sizes, int n_in,
                              void* d_out, int out_size)
{
    const float* x = (const float*)d_in[0];
    const float* w = (const float*)d_in[1];
    float* out     = (float*)d_out;

    const int smem_bytes = STAGES * XBUF * 4   // x ring: 58,752 B
                         + NCO * CIN * 10 * 8; // weight pairs: 40,960 B -> 99,712 B
    cudaFuncSetAttribute(convlif_kernel,
                         cudaFuncAttributeMaxDynamicSharedMemorySize, smem_bytes);

    dim3 grid(4 /* 2x2 spatial tiles */, BATCH, COUT / NCO);
    convlif_kernel<<<grid, THREADS, smem_bytes>>>(x, w, out);
}